// round 6
// baseline (speedup 1.0000x reference)
#include <cuda_runtime.h>
#include <stdint.h>

// ---------------- scratch (static __device__, no allocs) ----------------
__device__ float    g_partial[64];
__device__ unsigned g_w1b[64];                     // 27 bits: c*9 + kh*3 + kw
__device__ unsigned g_w2b[128 * 18];               // [jout][tap][jin][oo]
__device__ unsigned g_w3b[256 * 36];               // [o][t][jw]
__device__ __align__(16) unsigned g_wfb[1000 * 8]; // [k][j] 256 bits
__device__ unsigned g_xb[32 * 3 * 224 * 7];        // x sign bits: [n][ch][row][7 words]
__device__ uint2    g_a1b[32 * 112 * 112];         // layer1 sign bits, 64 ch
__device__ uint4    g_a2b[32 * 56 * 56];           // layer2 sign bits, 128 ch
__device__ __align__(16) unsigned char g_pb[32 * 32]; // pooled sign bits, byte = 8 ch

// alpha^2 for layer t, recomputed deterministically from fixed-order partials
__device__ __forceinline__ float alpha2_of(int t) {
    float s = 0.f;
    #pragma unroll
    for (int j = 0; j < 16; j++) s += g_partial[t * 16 + j];
    const float Ns[4] = {1728.f, 73728.f, 294912.f, 256000.f};
    float a = s / Ns[t];
    return a * a;
}

// max integer I with fmaf(a, I, b) < 0   (a > 0, exact by fix-up)
__device__ __forceinline__ int sign_thresh_I(float a, float b) {
    float t = -b / a;
    t = fminf(fmaxf(t, -4000.f), 4000.f);
    int I0 = (int)floorf(t);
    #pragma unroll
    for (int it = 0; it < 2; it++) if (fmaf(a, (float)(I0 + 1), b) < 0.f) I0++;
    #pragma unroll
    for (int it = 0; it < 2; it++) if (fmaf(a, (float)I0, b) >= 0.f) I0--;
    return I0;
}
// max integer I with fmaf(a, I, b) <= lim
__device__ __forceinline__ int max_I_leq(float a, float b, float lim) {
    float t = (lim - b) / a;
    t = fminf(fmaxf(t, -4000.f), 4000.f);
    int I = (int)floorf(t);
    #pragma unroll
    for (int it = 0; it < 2; it++) if (fmaf(a, (float)(I + 1), b) <= lim) I++;
    #pragma unroll
    for (int it = 0; it < 2; it++) if (fmaf(a, (float)I, b) > lim) I--;
    return I;
}
// min integer I with fmaf(a, I, b) >= lim
__device__ __forceinline__ int min_I_geq(float a, float b, float lim) {
    float t = (lim - b) / a;
    t = fminf(fmaxf(t, -4000.f), 4000.f);
    int I = (int)ceilf(t);
    #pragma unroll
    for (int it = 0; it < 2; it++) if (fmaf(a, (float)(I - 1), b) >= lim) I--;
    #pragma unroll
    for (int it = 0; it < 2; it++) if (fmaf(a, (float)I, b) < lim) I++;
    return I;
}

// ---------------- prep: alpha partials + all weight bit-packing, one launch ----------------
__global__ void __launch_bounds__(256) k_prep(const float* __restrict__ w1,
                                              const float* __restrict__ w2,
                                              const float* __restrict__ w3,
                                              const float* __restrict__ wf) {
    int b = blockIdx.x, tid = threadIdx.x;
    if (b < 64) {                                   // abs-sum partials
        int t = b >> 4, j = b & 15;
        const float* p; int N;
        if      (t == 0) { p = w1; N = 1728;   }
        else if (t == 1) { p = w2; N = 73728;  }
        else if (t == 2) { p = w3; N = 294912; }
        else             { p = wf; N = 256000; }
        float s = 0.f;
        for (int i = j * 256 + tid; i < N; i += 16 * 256) s += fabsf(p[i]);
        __shared__ float sh[256];
        sh[tid] = s; __syncthreads();
        for (int k = 128; k > 0; k >>= 1) {
            if (tid < k) sh[tid] += sh[tid + k];
            __syncthreads();
        }
        if (tid == 0) g_partial[b] = sh[0];
    } else if (b == 64) {                           // pack w1
        if (tid < 64) {
            int o = tid;
            unsigned bb = 0;
            for (int t = 0; t < 27; t++) if (w1[o * 27 + t] < 0.f) bb |= 1u << t;
            g_w1b[o] = bb;
        }
    } else if (b < 74) {                            // pack w2: 2304 ids -> [jout][t][jin][oo]
        int id = (b - 65) * 256 + tid;
        if (id < 128 * 18) {
            int o = id / 18, r = id % 18, t = r >> 1, j = r & 1;
            unsigned bb = 0;
            for (int c = 0; c < 32; c++)
                if (w2[o * 576 + (j * 32 + c) * 9 + t] < 0.f) bb |= 1u << c;
            g_w2b[((o >> 5) * 18 + t * 2 + j) * 32 + (o & 31)] = bb;
        }
    } else if (b < 110) {                           // pack w3: 9216 ids
        int id = (b - 74) * 256 + tid;
        if (id < 256 * 36) {
            int o = id / 36, r = id % 36, t = r >> 2, j = r & 3;
            unsigned bb = 0;
            for (int c = 0; c < 32; c++)
                if (w3[o * 1152 + (j * 32 + c) * 9 + t] < 0.f) bb |= 1u << c;
            g_w3b[o * 36 + t * 4 + j] = bb;
        }
    } else {                                        // pack wf: 8000 ids
        int id = (b - 110) * 256 + tid;
        if (id < 1000 * 8) {
            int k = id / 8, j = id % 8;
            unsigned bb = 0;
            for (int c = 0; c < 32; c++)
                if (wf[k * 256 + j * 32 + c] < 0.f) bb |= 1u << c;
            g_wfb[k * 8 + j] = bb;
        }
    }
}

// ---------------- pack x sign bits: 150528 words, 32 floats per word ----------------
__global__ void __launch_bounds__(256) k_packx(const float4* __restrict__ x) {
    int w = blockIdx.x * 256 + threadIdx.x;         // 588*256 = 150528 exact
    const float4* p = x + (size_t)w * 8;
    unsigned b = 0;
    #pragma unroll
    for (int i = 0; i < 8; i++) {
        float4 v = p[i];
        b |= (unsigned)(v.x < 0.f) << (4 * i)
           | (unsigned)(v.y < 0.f) << (4 * i + 1)
           | (unsigned)(v.z < 0.f) << (4 * i + 2)
           | (unsigned)(v.w < 0.f) << (4 * i + 3);
    }
    g_xb[w] = b;
}

// ---------------- layer 1 from bits: 4 output px per thread, integer thresholds ----------------
__global__ void __launch_bounds__(128) k_conv1b(const float* __restrict__ b1) {
    __shared__ unsigned sw[64];                     // bits 0..26 weights, 27..31 threshold
    __shared__ float    sb[64];
    __shared__ float    sh_a;
    if (threadIdx.x == 0) sh_a = alpha2_of(0);
    if (threadIdx.x < 64) {
        int o = threadIdx.x;
        float a = alpha2_of(0);
        float bo = b1[o];
        int I0 = sign_thresh_I(a, bo);
        int thr = (28 - I0) >> 1;                   // ceil((27 - I0)/2), V=27 interior
        thr = thr < 0 ? 0 : (thr > 28 ? 28 : thr);
        sw[o] = (g_w1b[o] & 0x07FFFFFFu) | ((unsigned)thr << 27);
        sb[o] = bo;
    }
    __syncthreads();

    int t = blockIdx.x * 128 + threadIdx.x;         // 100352 exact
    int n = t / 3136, r = t % 3136;                 // 3136 = 112 rows * 28 groups
    int oh = r / 28, g = r % 28;
    int ow0 = g * 4;
    float a1sq = sh_a;

    int cb = 2 * ow0 - 1;                           // leftmost input col (may be -1)
    int a = cb >> 5;
    int shft = cb - (a << 5);

    unsigned long long W[9];
    #pragma unroll
    for (int ch = 0; ch < 3; ch++)
        #pragma unroll
        for (int kh = 0; kh < 3; kh++) {
            int ih = 2 * oh - 1 + kh;
            unsigned w0 = 0, w1 = 0;
            if (ih >= 0) {
                int rowbase = ((n * 3 + ch) * 224 + ih) * 7;
                if (a >= 0)     w0 = g_xb[rowbase + a];
                if (a + 1 <= 6) w1 = g_xb[rowbase + a + 1];
            }
            W[ch * 3 + kh] = ((unsigned long long)w1 << 32) | w0;
        }

    bool rowslow = (oh == 0);
    uint2* outp = g_a1b + (n * 112 + oh) * 112 + ow0;
    #pragma unroll
    for (int k = 0; k < 4; k++) {
        unsigned xb = 0;
        #pragma unroll
        for (int ch = 0; ch < 3; ch++)
            #pragma unroll
            for (int kh = 0; kh < 3; kh++) {
                unsigned bits = (unsigned)(W[ch * 3 + kh] >> (shft + 2 * k)) & 7u;
                xb |= bits << (ch * 9 + kh * 3);
            }
        unsigned wo0 = 0, wo1 = 0;
        if (!rowslow && !(k == 0 && ow0 == 0)) {    // interior: pure integer path
            #pragma unroll 4
            for (int o = 0; o < 32; o++) {
                unsigned wA = sw[o];
                int p = __popc((xb ^ wA) & 0x07FFFFFFu);
                wo0 |= (unsigned)(p >= (int)(wA >> 27)) << o;
                unsigned wB = sw[32 + o];
                int p1 = __popc((xb ^ wB) & 0x07FFFFFFu);
                wo1 |= (unsigned)(p1 >= (int)(wB >> 27)) << o;
            }
        } else {                                    // border: FP path (rare)
            unsigned mask = 0x7FFFFFFu;
            if (rowslow) mask &= ~0x1C0E07u;
            if (k == 0 && ow0 == 0) mask &= ~0x1249249u;
            int V = __popc(mask);
            #pragma unroll 4
            for (int o = 0; o < 32; o++) {
                int p = __popc((xb ^ sw[o]) & mask);
                float y = fmaf(a1sq, (float)(V - 2 * p), sb[o]);
                wo0 |= (unsigned)(y < 0.f) << o;
                int p1 = __popc((xb ^ sw[32 + o]) & mask);
                float y1 = fmaf(a1sq, (float)(V - 2 * p1), sb[32 + o]);
                wo1 |= (unsigned)(y1 < 0.f) << o;
            }
        }
        outp[k] = make_uint2(wo0, wo1);
    }
}

// ---------------- layer 2: ballot scheme, pixel pairs, integer thresholds ----------------
__global__ void __launch_bounds__(256, 5) k_conv2(const float* __restrict__ b2) {
    __shared__ uint2 srow[3][114];                  // input row tile, zero-padded
    __shared__ float sh_a;
    int blk = blockIdx.x;                           // 1792 = 32*56
    int n = blk / 56, oh = blk % 56;
    int tid = threadIdx.x, lane = tid & 31, w = tid >> 5;
    int jout = w & 3, half = w >> 2;

    if (tid == 0) sh_a = alpha2_of(1);
    for (int i = tid; i < 342; i += 256) {
        int kh = i / 114, col = i % 114;
        int ih = 2 * oh - 1 + kh, iw = col - 1;
        uint2 v = make_uint2(0u, 0u);
        if ((unsigned)ih < 112u && (unsigned)iw < 112u)
            v = g_a1b[(n * 112 + ih) * 112 + iw];
        srow[kh][col] = v;
    }

    unsigned wreg[18];
    #pragma unroll
    for (int i = 0; i < 18; i++) wreg[i] = g_w2b[(jout * 18 + i) * 32 + lane];
    float bb = b2[jout * 32 + lane];

    int pR = 0, pC = 0;
    #pragma unroll
    for (int t = 0; t < 3; t++) pR += __popc(wreg[t * 2]) + __popc(wreg[t * 2 + 1]);
    #pragma unroll
    for (int k = 0; k < 3; k++) pC += __popc(wreg[k * 6]) + __popc(wreg[k * 6 + 1]);
    int pT0 = __popc(wreg[0]) + __popc(wreg[1]);
    __syncthreads();

    float a2sq = sh_a;
    int rowflag = (oh == 0);
    int rAdj = rowflag ? pR : 0;
    int Vrow = rowflag ? 2 : 3;
    int I0 = sign_thresh_I(a2sq, bb);
    int thrA = (64 * Vrow * 3 + 2 * rAdj - I0 + 1) >> 1;      // interior cols
    int adj0 = rAdj + pC - (rowflag ? pT0 : 0);
    int thr0 = (64 * Vrow * 2 + 2 * adj0 - I0 + 1) >> 1;      // ow==0 column

    unsigned* outp = (unsigned*)g_a2b + (size_t)(n * 56 + oh) * 56 * 4 + jout;
    #pragma unroll 2
    for (int ip = 0; ip < 14; ip++) {
        int ow_a = half * 28 + 2 * ip;
        int b0 = 2 * ow_a;                          // smem col base; window cols b0..b0+4
        int P0 = 0, P1 = 0;
        #pragma unroll
        for (int kh = 0; kh < 3; kh++) {
            uint2 c0 = srow[kh][b0],     c1 = srow[kh][b0 + 1], c2 = srow[kh][b0 + 2];
            uint2 c3 = srow[kh][b0 + 3], c4 = srow[kh][b0 + 4];
            unsigned w0 = wreg[kh * 6],     w1 = wreg[kh * 6 + 1];
            unsigned w2 = wreg[kh * 6 + 2], w3 = wreg[kh * 6 + 3];
            unsigned w4 = wreg[kh * 6 + 4], w5 = wreg[kh * 6 + 5];
            P0 += __popc(c0.x ^ w0) + __popc(c0.y ^ w1)
                + __popc(c1.x ^ w2) + __popc(c1.y ^ w3)
                + __popc(c2.x ^ w4) + __popc(c2.y ^ w5);
            P1 += __popc(c2.x ^ w0) + __popc(c2.y ^ w1)
                + __popc(c3.x ^ w2) + __popc(c3.y ^ w3)
                + __popc(c4.x ^ w4) + __popc(c4.y ^ w5);
        }
        int thra = (half == 0 && ip == 0) ? thr0 : thrA;
        unsigned word0 = __ballot_sync(0xffffffffu, P0 >= thra);
        unsigned word1 = __ballot_sync(0xffffffffu, P1 >= thrA);
        if (lane == 0) {
            outp[ow_a * 4] = word0;
            outp[(ow_a + 1) * 4] = word1;
        }
    }
}

// ---------------- layer 3: tap-outer, integer clip screen, fused pooled sign ----------------
__global__ void __launch_bounds__(256, 5) k_conv3(const float* __restrict__ b3) {
    int n = blockIdx.x >> 5, g = blockIdx.x & 31;   // octet g: channels g*8..g*8+7
    __shared__ unsigned sw[288];
    __shared__ float    sb[8];
    __shared__ int      ssum[8];                    // sum of adjusted P
    __shared__ float    scorr[8];
    __shared__ float    sh_a;
    __shared__ int      sR[8], sC[8], sT0[8];
    __shared__ int      sPloMax, sRngMin, sILoMax, sIHiMin;
    __shared__ int      sILo[8], sIHi[8];
    __shared__ int      sflag;
    for (int i = threadIdx.x; i < 288; i += 256) sw[i] = g_w3b[g * 288 + i];
    if (threadIdx.x < 8) {
        sb[threadIdx.x] = b3[g * 8 + threadIdx.x];
        ssum[threadIdx.x] = 0;
        scorr[threadIdx.x] = 0.f;
    }
    if (threadIdx.x == 0) { sh_a = alpha2_of(2); sflag = 0; }
    __syncthreads();
    if (threadIdx.x < 8) {
        int c = threadIdx.x;
        int rr = 0, cc = 0;
        #pragma unroll
        for (int t = 0; t < 3; t++)
            rr += __popc(sw[c*36+t*4]) + __popc(sw[c*36+t*4+1]) + __popc(sw[c*36+t*4+2]) + __popc(sw[c*36+t*4+3]);
        #pragma unroll
        for (int kk = 0; kk < 3; kk++) {
            int t = kk * 3;
            cc += __popc(sw[c*36+t*4]) + __popc(sw[c*36+t*4+1]) + __popc(sw[c*36+t*4+2]) + __popc(sw[c*36+t*4+3]);
        }
        sR[c] = rr; sC[c] = cc;
        sT0[c] = __popc(sw[c*36]) + __popc(sw[c*36+1]) + __popc(sw[c*36+2]) + __popc(sw[c*36+3]);
        float a = sh_a, bo = sb[c];
        sIHi[c] = max_I_leq(a, bo, 1.f);            // y <= 1  <=>  I <= Ihi
        sILo[c] = min_I_geq(a, bo, -1.f);           // y >= -1 <=>  I >= Ilo
    }
    __syncthreads();
    if (threadIdx.x == 0) {
        int plo = -1000000, phi = 1000000, ilo = -1000000, ihi = 1000000;
        #pragma unroll
        for (int c = 0; c < 8; c++) {
            int PloC = (1152 - sIHi[c] + 1) >> 1;
            int PhiC = (1152 - sILo[c]) >> 1;
            plo = PloC > plo ? PloC : plo;
            phi = PhiC < phi ? PhiC : phi;
            ilo = sILo[c] > ilo ? sILo[c] : ilo;
            ihi = sIHi[c] < ihi ? sIHi[c] : ihi;
        }
        sPloMax = plo; sRngMin = phi - plo; sILoMax = ilo; sIHiMin = ihi;
    }
    __syncthreads();

    int ploM = sPloMax, rngM = sRngMin, iloM = sILoMax, ihiM = sIHiMin;
    int accP[8];
    #pragma unroll
    for (int c = 0; c < 8; c++) accP[c] = 0;
    int flag = 0;
    const uint4* src = g_a2b + n * 3136;

    for (int pix = threadIdx.x; pix < 784; pix += 256) {
        int oh = pix / 28, ow = pix % 28;
        int base = (2 * oh - 1) * 56 + (2 * ow - 1);
        int P[8];
        #pragma unroll
        for (int c = 0; c < 8; c++) P[c] = 0;
        #pragma unroll
        for (int t = 0; t < 9; t++) {
            int kh = t / 3, kw = t % 3;
            uint4 av = make_uint4(0u, 0u, 0u, 0u);
            if ((kh | oh) && (kw | ow))
                av = src[base + kh * 56 + kw];
            #pragma unroll
            for (int c = 0; c < 8; c++) {
                const unsigned* wp = &sw[c * 36 + t * 4];
                P[c] += __popc(av.x ^ wp[0]) + __popc(av.y ^ wp[1])
                      + __popc(av.z ^ wp[2]) + __popc(av.w ^ wp[3]);
            }
        }
        if (oh > 0 && ow > 0) {                     // interior: pure integer
            #pragma unroll
            for (int c = 0; c < 8; c++) {
                accP[c] += P[c];
                flag |= (unsigned)(P[c] - ploM) > (unsigned)rngM;
            }
        } else {                                    // border: adjust, integer screen
            int rv = oh ? 3 : 2, cv = ow ? 3 : 2;
            int V = 128 * rv * cv;
            #pragma unroll
            for (int c = 0; c < 8; c++) {
                int adj = (oh ? 0 : sR[c]) + (ow ? 0 : sC[c]) - ((oh | ow) ? 0 : sT0[c]);
                int Pa = P[c] - adj;
                accP[c] += Pa;
                int I = V - 2 * Pa;
                flag |= (I < iloM) | (I > ihiM);
            }
        }
    }
    if (flag) atomicOr(&sflag, 1);

    #pragma unroll
    for (int c = 0; c < 8; c++) {
        int v = accP[c];
        #pragma unroll
        for (int s = 16; s > 0; s >>= 1) v += __shfl_xor_sync(0xffffffffu, v, s);
        if ((threadIdx.x & 31) == 0) atomicAdd(&ssum[c], v);
    }
    __syncthreads();

    if (sflag) {                                    // exact FP slow path (never in practice)
        float a3sq = sh_a;
        for (int pix = threadIdx.x; pix < 784; pix += 256) {
            int oh = pix / 28, ow = pix % 28;
            int base = (2 * oh - 1) * 56 + (2 * ow - 1);
            int P[8];
            #pragma unroll
            for (int c = 0; c < 8; c++) P[c] = 0;
            #pragma unroll
            for (int t = 0; t < 9; t++) {
                int kh = t / 3, kw = t % 3;
                uint4 av = make_uint4(0u, 0u, 0u, 0u);
                if ((kh | oh) && (kw | ow))
                    av = src[base + kh * 56 + kw];
                #pragma unroll
                for (int c = 0; c < 8; c++) {
                    const unsigned* wp = &sw[c * 36 + t * 4];
                    P[c] += __popc(av.x ^ wp[0]) + __popc(av.y ^ wp[1])
                          + __popc(av.z ^ wp[2]) + __popc(av.w ^ wp[3]);
                }
            }
            int rv = oh ? 3 : 2, cv = ow ? 3 : 2;
            int V = 128 * rv * cv;
            #pragma unroll
            for (int c = 0; c < 8; c++) {
                int adj = (oh ? 0 : sR[c]) + (ow ? 0 : sC[c]) - ((oh | ow) ? 0 : sT0[c]);
                int I = V - 2 * (P[c] - adj);
                float y = fmaf(a3sq, (float)I, sb[c]);
                if (fabsf(y) > 1.f) atomicAdd(&scorr[c], (y > 0.f ? 1.f : -1.f) - y);
            }
        }
        __syncthreads();
    }

    if (threadIdx.x < 8) {
        int c = threadIdx.x;
        float a3sq = sh_a;
        int sumI = 881792 - 2 * ssum[c];            // sum V over 784 px is constant
        float val = fmaf(a3sq, (float)sumI, 784.f * sb[c] + scorr[c]);
        unsigned m = __ballot_sync(0xffu, val < 0.f) & 0xffu;
        if (c == 0) g_pb[n * 32 + g] = (unsigned char)m;
    }
}

// ---------------- FC: out[n,k] = af^2 * (256 - 2P) + bf[k] ----------------
__global__ void __launch_bounds__(128) k_fc(const float* __restrict__ bf, float* __restrict__ out) {
    __shared__ float sh_a;
    if (threadIdx.x == 0) sh_a = alpha2_of(3);
    __syncthreads();
    int idx = blockIdx.x * 128 + threadIdx.x;
    if (idx >= 32000) return;
    int n = idx / 1000, k = idx % 1000;
    float afsq = sh_a;
    const uint4* pb = (const uint4*)(g_pb + n * 32);
    const uint4* wb = (const uint4*)(g_wfb + k * 8);
    uint4 p0 = pb[0], p1 = pb[1], w0 = wb[0], w1 = wb[1];
    int P = __popc(p0.x ^ w0.x) + __popc(p0.y ^ w0.y) + __popc(p0.z ^ w0.z) + __popc(p0.w ^ w0.w)
          + __popc(p1.x ^ w1.x) + __popc(p1.y ^ w1.y) + __popc(p1.z ^ w1.z) + __popc(p1.w ^ w1.w);
    out[idx] = fmaf(afsq, (float)(256 - 2 * P), bf[k]);
}

// ---------------- launch ----------------
extern "C" void kernel_launch(void* const* d_in, const int* in_sizes, int n_in,
                              void* d_out, int out_size) {
    const float* x  = (const float*)d_in[0];
    const float* w1 = (const float*)d_in[1];
    const float* b1 = (const float*)d_in[2];
    const float* w2 = (const float*)d_in[3];
    const float* b2 = (const float*)d_in[4];
    const float* w3 = (const float*)d_in[5];
    const float* b3 = (const float*)d_in[6];
    const float* wf = (const float*)d_in[7];
    const float* bf = (const float*)d_in[8];
    float* out = (float*)d_out;

    k_prep<<<142, 256>>>(w1, w2, w3, wf);
    k_packx<<<588, 256>>>((const float4*)x);
    k_conv1b<<<784, 128>>>(b1);
    k_conv2<<<1792, 256>>>(b2);
    k_conv3<<<1024, 256>>>(b3);
    k_fc<<<250, 128>>>(bf, out);
}

// round 11
// speedup vs baseline: 2.3110x; 2.3110x over previous
#include <cuda_runtime.h>
#include <stdint.h>

// ---------------- scratch (static __device__, no allocs) ----------------
__device__ float    g_partial[64];
__device__ unsigned g_w1b[64];                     // 27 bits: c*9 + kh*3 + kw
__device__ unsigned g_w2b[128 * 18];               // [jout][tap][jin][oo]
__device__ unsigned g_w3b[256 * 36];               // [o][t][jw]
__device__ __align__(16) unsigned g_wfb[1000 * 8]; // [k][j] 256 bits
__device__ unsigned g_xb[32 * 3 * 224 * 7];        // x sign bits: [n][ch][row][7 words]
__device__ uint2    g_a1b[32 * 112 * 112];         // layer1 sign bits, 64 ch
__device__ uint4    g_a2b[32 * 56 * 56];           // layer2 sign bits, 128 ch
__device__ __align__(16) unsigned char g_pb[32 * 32]; // pooled sign bits, byte = 8 ch

// alpha^2 for layer t, recomputed deterministically from fixed-order partials
__device__ __forceinline__ float alpha2_of(int t) {
    float s = 0.f;
    #pragma unroll
    for (int j = 0; j < 16; j++) s += g_partial[t * 16 + j];
    const float Ns[4] = {1728.f, 73728.f, 294912.f, 256000.f};
    float a = s / Ns[t];
    return a * a;
}

// max integer I with fmaf(a, I, b) < 0   (a > 0, exact by fix-up)
__device__ __forceinline__ int sign_thresh_I(float a, float b) {
    float t = -b / a;
    t = fminf(fmaxf(t, -4000.f), 4000.f);
    int I0 = (int)floorf(t);
    #pragma unroll
    for (int it = 0; it < 2; it++) if (fmaf(a, (float)(I0 + 1), b) < 0.f) I0++;
    #pragma unroll
    for (int it = 0; it < 2; it++) if (fmaf(a, (float)I0, b) >= 0.f) I0--;
    return I0;
}

// ---------------- prep: alpha partials + weight packing + x packing, one launch ----------------
__global__ void __launch_bounds__(256) k_prep(const float* __restrict__ w1,
                                              const float* __restrict__ w2,
                                              const float* __restrict__ w3,
                                              const float* __restrict__ wf,
                                              const float4* __restrict__ x) {
    int b = blockIdx.x, tid = threadIdx.x;
    if (b < 64) {                                   // abs-sum partials
        int t = b >> 4, j = b & 15;
        const float* p; int N;
        if      (t == 0) { p = w1; N = 1728;   }
        else if (t == 1) { p = w2; N = 73728;  }
        else if (t == 2) { p = w3; N = 294912; }
        else             { p = wf; N = 256000; }
        float s = 0.f;
        for (int i = j * 256 + tid; i < N; i += 16 * 256) s += fabsf(p[i]);
        __shared__ float sh[256];
        sh[tid] = s; __syncthreads();
        for (int k = 128; k > 0; k >>= 1) {
            if (tid < k) sh[tid] += sh[tid + k];
            __syncthreads();
        }
        if (tid == 0) g_partial[b] = sh[0];
    } else if (b == 64) {                           // pack w1
        if (tid < 64) {
            int o = tid;
            unsigned bb = 0;
            for (int t = 0; t < 27; t++) if (w1[o * 27 + t] < 0.f) bb |= 1u << t;
            g_w1b[o] = bb;
        }
    } else if (b < 74) {                            // pack w2: 2304 ids -> [jout][t][jin][oo]
        int id = (b - 65) * 256 + tid;
        if (id < 128 * 18) {
            int o = id / 18, r = id % 18, t = r >> 1, j = r & 1;
            unsigned bb = 0;
            for (int c = 0; c < 32; c++)
                if (w2[o * 576 + (j * 32 + c) * 9 + t] < 0.f) bb |= 1u << c;
            g_w2b[((o >> 5) * 18 + t * 2 + j) * 32 + (o & 31)] = bb;
        }
    } else if (b < 110) {                           // pack w3: 9216 ids
        int id = (b - 74) * 256 + tid;
        if (id < 256 * 36) {
            int o = id / 36, r = id % 36, t = r >> 2, j = r & 3;
            unsigned bb = 0;
            for (int c = 0; c < 32; c++)
                if (w3[o * 1152 + (j * 32 + c) * 9 + t] < 0.f) bb |= 1u << c;
            g_w3b[o * 36 + t * 4 + j] = bb;
        }
    } else if (b < 142) {                           // pack wf: 8000 ids
        int id = (b - 110) * 256 + tid;
        if (id < 1000 * 8) {
            int k = id / 8, j = id % 8;
            unsigned bb = 0;
            for (int c = 0; c < 32; c++)
                if (wf[k * 256 + j * 32 + c] < 0.f) bb |= 1u << c;
            g_wfb[k * 8 + j] = bb;
        }
    } else {                                        // pack x: 150528 words
        int w = (b - 142) * 256 + tid;
        const float4* p = x + (size_t)w * 8;
        unsigned bb = 0;
        #pragma unroll
        for (int i = 0; i < 8; i++) {
            float4 v = p[i];
            bb |= (unsigned)(v.x < 0.f) << (4 * i)
                | (unsigned)(v.y < 0.f) << (4 * i + 1)
                | (unsigned)(v.z < 0.f) << (4 * i + 2)
                | (unsigned)(v.w < 0.f) << (4 * i + 3);
        }
        g_xb[w] = bb;
    }
}

// ---------------- layer 1 from bits: 4 output px per thread, integer thresholds ----------------
__global__ void __launch_bounds__(128) k_conv1b(const float* __restrict__ b1) {
    __shared__ unsigned sw[64];                     // bits 0..26 weights, 27..31 threshold
    __shared__ float    sb[64];
    __shared__ float    sh_a;
    if (threadIdx.x == 0) sh_a = alpha2_of(0);
    if (threadIdx.x < 64) {
        int o = threadIdx.x;
        float a = alpha2_of(0);
        float bo = b1[o];
        int I0 = sign_thresh_I(a, bo);
        int thr = (28 - I0) >> 1;                   // ceil((27 - I0)/2), V=27 interior
        thr = thr < 0 ? 0 : (thr > 28 ? 28 : thr);
        sw[o] = (g_w1b[o] & 0x07FFFFFFu) | ((unsigned)thr << 27);
        sb[o] = bo;
    }
    __syncthreads();

    int t = blockIdx.x * 128 + threadIdx.x;         // 100352 exact
    int n = t / 3136, r = t % 3136;                 // 3136 = 112 rows * 28 groups
    int oh = r / 28, g = r % 28;
    int ow0 = g * 4;
    float a1sq = sh_a;

    int cb = 2 * ow0 - 1;                           // leftmost input col (may be -1)
    int a = cb >> 5;
    int shft = cb - (a << 5);

    unsigned long long W[9];
    #pragma unroll
    for (int ch = 0; ch < 3; ch++)
        #pragma unroll
        for (int kh = 0; kh < 3; kh++) {
            int ih = 2 * oh - 1 + kh;
            unsigned w0 = 0, w1 = 0;
            if (ih >= 0) {
                int rowbase = ((n * 3 + ch) * 224 + ih) * 7;
                if (a >= 0)     w0 = g_xb[rowbase + a];
                if (a + 1 <= 6) w1 = g_xb[rowbase + a + 1];
            }
            W[ch * 3 + kh] = ((unsigned long long)w1 << 32) | w0;
        }

    bool rowslow = (oh == 0);
    uint2* outp = g_a1b + (n * 112 + oh) * 112 + ow0;
    #pragma unroll
    for (int k = 0; k < 4; k++) {
        unsigned xb = 0;
        #pragma unroll
        for (int ch = 0; ch < 3; ch++)
            #pragma unroll
            for (int kh = 0; kh < 3; kh++) {
                unsigned bits = (unsigned)(W[ch * 3 + kh] >> (shft + 2 * k)) & 7u;
                xb |= bits << (ch * 9 + kh * 3);
            }
        unsigned wo0 = 0, wo1 = 0;
        if (!rowslow && !(k == 0 && ow0 == 0)) {    // interior: pure integer path
            #pragma unroll 4
            for (int o = 0; o < 32; o++) {
                unsigned wA = sw[o];
                int p = __popc((xb ^ wA) & 0x07FFFFFFu);
                wo0 |= (unsigned)(p >= (int)(wA >> 27)) << o;
                unsigned wB = sw[32 + o];
                int p1 = __popc((xb ^ wB) & 0x07FFFFFFu);
                wo1 |= (unsigned)(p1 >= (int)(wB >> 27)) << o;
            }
        } else {                                    // border: FP path (rare)
            unsigned mask = 0x7FFFFFFu;
            if (rowslow) mask &= ~0x1C0E07u;
            if (k == 0 && ow0 == 0) mask &= ~0x1249249u;
            int V = __popc(mask);
            #pragma unroll 4
            for (int o = 0; o < 32; o++) {
                int p = __popc((xb ^ sw[o]) & mask);
                float y = fmaf(a1sq, (float)(V - 2 * p), sb[o]);
                wo0 |= (unsigned)(y < 0.f) << o;
                int p1 = __popc((xb ^ sw[32 + o]) & mask);
                float y1 = fmaf(a1sq, (float)(V - 2 * p1), sb[32 + o]);
                wo1 |= (unsigned)(y1 < 0.f) << o;
            }
        }
        outp[k] = make_uint2(wo0, wo1);
    }
}

// ---------------- layer 2: ballot scheme, pixel pairs, integer thresholds ----------------
__global__ void __launch_bounds__(256, 5) k_conv2(const float* __restrict__ b2) {
    __shared__ uint2 srow[3][114];                  // input row tile, zero-padded
    __shared__ float sh_a;
    int blk = blockIdx.x;                           // 1792 = 32*56
    int n = blk / 56, oh = blk % 56;
    int tid = threadIdx.x, lane = tid & 31, w = tid >> 5;
    int jout = w & 3, half = w >> 2;

    if (tid == 0) sh_a = alpha2_of(1);
    for (int i = tid; i < 342; i += 256) {
        int kh = i / 114, col = i % 114;
        int ih = 2 * oh - 1 + kh, iw = col - 1;
        uint2 v = make_uint2(0u, 0u);
        if ((unsigned)ih < 112u && (unsigned)iw < 112u)
            v = g_a1b[(n * 112 + ih) * 112 + iw];
        srow[kh][col] = v;
    }

    unsigned wreg[18];
    #pragma unroll
    for (int i = 0; i < 18; i++) wreg[i] = g_w2b[(jout * 18 + i) * 32 + lane];
    float bb = b2[jout * 32 + lane];

    int pR = 0, pC = 0;
    #pragma unroll
    for (int t = 0; t < 3; t++) pR += __popc(wreg[t * 2]) + __popc(wreg[t * 2 + 1]);
    #pragma unroll
    for (int k = 0; k < 3; k++) pC += __popc(wreg[k * 6]) + __popc(wreg[k * 6 + 1]);
    int pT0 = __popc(wreg[0]) + __popc(wreg[1]);
    __syncthreads();

    float a2sq = sh_a;
    int rowflag = (oh == 0);
    int rAdj = rowflag ? pR : 0;
    int Vrow = rowflag ? 2 : 3;
    int I0 = sign_thresh_I(a2sq, bb);
    int thrA = (64 * Vrow * 3 + 2 * rAdj - I0 + 1) >> 1;      // interior cols
    int adj0 = rAdj + pC - (rowflag ? pT0 : 0);
    int thr0 = (64 * Vrow * 2 + 2 * adj0 - I0 + 1) >> 1;      // ow==0 column

    unsigned* outp = (unsigned*)g_a2b + (size_t)(n * 56 + oh) * 56 * 4 + jout;
    #pragma unroll 2
    for (int ip = 0; ip < 14; ip++) {
        int ow_a = half * 28 + 2 * ip;
        int b0 = 2 * ow_a;                          // smem col base; window cols b0..b0+4
        int P0 = 0, P1 = 0;
        #pragma unroll
        for (int kh = 0; kh < 3; kh++) {
            uint2 c0 = srow[kh][b0],     c1 = srow[kh][b0 + 1], c2 = srow[kh][b0 + 2];
            uint2 c3 = srow[kh][b0 + 3], c4 = srow[kh][b0 + 4];
            unsigned w0 = wreg[kh * 6],     w1 = wreg[kh * 6 + 1];
            unsigned w2 = wreg[kh * 6 + 2], w3 = wreg[kh * 6 + 3];
            unsigned w4 = wreg[kh * 6 + 4], w5 = wreg[kh * 6 + 5];
            P0 += __popc(c0.x ^ w0) + __popc(c0.y ^ w1)
                + __popc(c1.x ^ w2) + __popc(c1.y ^ w3)
                + __popc(c2.x ^ w4) + __popc(c2.y ^ w5);
            P1 += __popc(c2.x ^ w0) + __popc(c2.y ^ w1)
                + __popc(c3.x ^ w2) + __popc(c3.y ^ w3)
                + __popc(c4.x ^ w4) + __popc(c4.y ^ w5);
        }
        int thra = (half == 0 && ip == 0) ? thr0 : thrA;
        unsigned word0 = __ballot_sync(0xffffffffu, P0 >= thra);
        unsigned word1 = __ballot_sync(0xffffffffu, P1 >= thrA);
        if (lane == 0) {
            outp[ow_a * 4] = word0;
            outp[(ow_a + 1) * 4] = word1;
        }
    }
}

// ---------------- layer 3: tap-outer XNOR conv 128->256 + fused pooled sign (R5 known-good) ----------------
__global__ void __launch_bounds__(256, 5) k_conv3(const float* __restrict__ b3) {
    int n = blockIdx.x >> 5, g = blockIdx.x & 31;   // octet g: channels g*8..g*8+7
    __shared__ unsigned sw[288];
    __shared__ float    sb[8];
    __shared__ int      ssum[8];
    __shared__ float    scorr[8];
    __shared__ float    sh_a;
    __shared__ int      sR[8], sC[8], sT0[8];       // border weight-popcount corrections
    for (int i = threadIdx.x; i < 288; i += 256) sw[i] = g_w3b[g * 288 + i];
    if (threadIdx.x < 8) {
        sb[threadIdx.x] = b3[g * 8 + threadIdx.x];
        ssum[threadIdx.x] = 0;
        scorr[threadIdx.x] = 0.f;
    }
    if (threadIdx.x == 0) sh_a = alpha2_of(2);
    __syncthreads();
    if (threadIdx.x < 8) {
        int c = threadIdx.x;
        int rr = 0, cc = 0;
        #pragma unroll
        for (int t = 0; t < 3; t++)                 // row 0 taps: 0,1,2
            rr += __popc(sw[c*36+t*4]) + __popc(sw[c*36+t*4+1]) + __popc(sw[c*36+t*4+2]) + __popc(sw[c*36+t*4+3]);
        #pragma unroll
        for (int kk = 0; kk < 3; kk++) {            // col 0 taps: 0,3,6
            int t = kk * 3;
            cc += __popc(sw[c*36+t*4]) + __popc(sw[c*36+t*4+1]) + __popc(sw[c*36+t*4+2]) + __popc(sw[c*36+t*4+3]);
        }
        sR[c] = rr; sC[c] = cc;
        sT0[c] = __popc(sw[c*36]) + __popc(sw[c*36+1]) + __popc(sw[c*36+2]) + __popc(sw[c*36+3]);
    }
    __syncthreads();

    float a3sq = sh_a;
    int acc[8];
    #pragma unroll
    for (int c = 0; c < 8; c++) acc[c] = 0;
    const uint4* src = g_a2b + n * 3136;

    for (int pix = threadIdx.x; pix < 784; pix += 256) {
        int oh = pix / 28, ow = pix % 28;
        int base = (2 * oh - 1) * 56 + (2 * ow - 1);
        int P[8];
        #pragma unroll
        for (int c = 0; c < 8; c++) P[c] = 0;
        #pragma unroll
        for (int t = 0; t < 9; t++) {
            int kh = t / 3, kw = t % 3;
            uint4 av = make_uint4(0u, 0u, 0u, 0u);
            if ((kh | oh) && (kw | ow))             // predicated LDG; off => av stays 0
                av = src[base + kh * 56 + kw];
            #pragma unroll
            for (int c = 0; c < 8; c++) {
                const unsigned* wp = &sw[c * 36 + t * 4];
                P[c] += __popc(av.x ^ wp[0]) + __popc(av.y ^ wp[1])
                      + __popc(av.z ^ wp[2]) + __popc(av.w ^ wp[3]);
            }
        }
        int V = 1152;
        if (oh == 0 || ow == 0) {                   // remove popc(w) from zeroed taps
            int rv = oh ? 3 : 2, cv = ow ? 3 : 2;
            V = 128 * rv * cv;
            #pragma unroll
            for (int c = 0; c < 8; c++) {
                int adj = 0;
                if (oh == 0) adj += sR[c];
                if (ow == 0) adj += sC[c];
                if (oh == 0 && ow == 0) adj -= sT0[c];
                P[c] -= adj;
            }
        }
        #pragma unroll
        for (int c = 0; c < 8; c++) {
            int I = V - 2 * P[c];
            acc[c] += I;
            float y = fmaf(a3sq, (float)I, sb[c]);
            if (fabsf(y) > 1.f) atomicAdd(&scorr[c], (y > 0.f ? 1.f : -1.f) - y);
        }
    }

    #pragma unroll
    for (int c = 0; c < 8; c++) {
        int v = acc[c];
        #pragma unroll
        for (int s = 16; s > 0; s >>= 1) v += __shfl_xor_sync(0xffffffffu, v, s);
        if ((threadIdx.x & 31) == 0) atomicAdd(&ssum[c], v);
    }
    __syncthreads();

    if (threadIdx.x < 8) {
        int c = threadIdx.x;
        float val = fmaf(a3sq, (float)ssum[c], 784.f * sb[c] + scorr[c]);
        unsigned m = __ballot_sync(0xffu, val < 0.f) & 0xffu;
        if (c == 0) g_pb[n * 32 + g] = (unsigned char)m;
    }
}

// ---------------- FC: out[n,k] = af^2 * (256 - 2P) + bf[k] ----------------
__global__ void __launch_bounds__(128) k_fc(const float* __restrict__ bf, float* __restrict__ out) {
    __shared__ float sh_a;
    if (threadIdx.x == 0) sh_a = alpha2_of(3);
    __syncthreads();
    int idx = blockIdx.x * 128 + threadIdx.x;
    if (idx >= 32000) return;
    int n = idx / 1000, k = idx % 1000;
    float afsq = sh_a;
    const uint4* pb = (const uint4*)(g_pb + n * 32);
    const uint4* wb = (const uint4*)(g_wfb + k * 8);
    uint4 p0 = pb[0], p1 = pb[1], w0 = wb[0], w1 = wb[1];
    int P = __popc(p0.x ^ w0.x) + __popc(p0.y ^ w0.y) + __popc(p0.z ^ w0.z) + __popc(p0.w ^ w0.w)
          + __popc(p1.x ^ w1.x) + __popc(p1.y ^ w1.y) + __popc(p1.z ^ w1.z) + __popc(p1.w ^ w1.w);
    out[idx] = fmaf(afsq, (float)(256 - 2 * P), bf[k]);
}

// ---------------- launch ----------------
extern "C" void kernel_launch(void* const* d_in, const int* in_sizes, int n_in,
                              void* d_out, int out_size) {
    const float* x  = (const float*)d_in[0];
    const float* w1 = (const float*)d_in[1];
    const float* b1 = (const float*)d_in[2];
    const float* w2 = (const float*)d_in[3];
    const float* b2 = (const float*)d_in[4];
    const float* w3 = (const float*)d_in[5];
    const float* b3 = (const float*)d_in[6];
    const float* wf = (const float*)d_in[7];
    const float* bf = (const float*)d_in[8];
    float* out = (float*)d_out;

    k_prep<<<730, 256>>>(w1, w2, w3, wf, (const float4*)x);
    k_conv1b<<<784, 128>>>(b1);
    k_conv2<<<1792, 256>>>(b2);
    k_conv3<<<1024, 256>>>(b3);
    k_fc<<<250, 128>>>(bf, out);
}

// round 12
// speedup vs baseline: 2.4365x; 1.0543x over previous
#include <cuda_runtime.h>
#include <stdint.h>

// ---------------- scratch (static __device__, no allocs) ----------------
__device__ float    g_partial[64];
__device__ unsigned g_w1b[64];                     // 27 bits: c*9 + kh*3 + kw
__device__ unsigned g_w2b[128 * 18];               // [jout][tap][jin][oo]
__device__ unsigned g_w3b[256 * 36];               // [tapword i][o]  (i = t*4+jw)
__device__ __align__(16) unsigned g_wfb[1000 * 8]; // [k][j] 256 bits
__device__ unsigned g_xb[32 * 3 * 224 * 7];        // x sign bits: [n][ch][row][7 words]
__device__ uint2    g_a1b[32 * 112 * 112];         // layer1 sign bits, 64 ch
__device__ uint4    g_a2b[32 * 56 * 56];           // layer2 sign bits, 128 ch
__device__ int      g_s3[32 * 256];                // conv3 pooled integer sums
__device__ float    g_c3[32 * 256];                // conv3 clip corrections (0 in practice)
__device__ __align__(16) unsigned char g_pb[32 * 32]; // pooled sign bits, byte = 8 ch

// alpha^2 for layer t, recomputed deterministically from fixed-order partials
__device__ __forceinline__ float alpha2_of(int t) {
    float s = 0.f;
    #pragma unroll
    for (int j = 0; j < 16; j++) s += g_partial[t * 16 + j];
    const float Ns[4] = {1728.f, 73728.f, 294912.f, 256000.f};
    float a = s / Ns[t];
    return a * a;
}

// max integer I with fmaf(a, I, b) < 0   (a > 0, exact by fix-up)
__device__ __forceinline__ int sign_thresh_I(float a, float b) {
    float t = -b / a;
    t = fminf(fmaxf(t, -4000.f), 4000.f);
    int I0 = (int)floorf(t);
    #pragma unroll
    for (int it = 0; it < 2; it++) if (fmaf(a, (float)(I0 + 1), b) < 0.f) I0++;
    #pragma unroll
    for (int it = 0; it < 2; it++) if (fmaf(a, (float)I0, b) >= 0.f) I0--;
    return I0;
}
// max integer I with fmaf(a, I, b) <= lim
__device__ __forceinline__ int max_I_leq(float a, float b, float lim) {
    float t = (lim - b) / a;
    t = fminf(fmaxf(t, -4000.f), 4000.f);
    int I = (int)floorf(t);
    #pragma unroll
    for (int it = 0; it < 2; it++) if (fmaf(a, (float)(I + 1), b) <= lim) I++;
    #pragma unroll
    for (int it = 0; it < 2; it++) if (fmaf(a, (float)I, b) > lim) I--;
    return I;
}
// min integer I with fmaf(a, I, b) >= lim
__device__ __forceinline__ int min_I_geq(float a, float b, float lim) {
    float t = (lim - b) / a;
    t = fminf(fmaxf(t, -4000.f), 4000.f);
    int I = (int)ceilf(t);
    #pragma unroll
    for (int it = 0; it < 2; it++) if (fmaf(a, (float)(I - 1), b) >= lim) I--;
    #pragma unroll
    for (int it = 0; it < 2; it++) if (fmaf(a, (float)I, b) < lim) I++;
    return I;
}

// ---------------- prep: alpha partials + weight packing + x packing + zeroing ----------------
__global__ void __launch_bounds__(256) k_prep(const float* __restrict__ w1,
                                              const float* __restrict__ w2,
                                              const float* __restrict__ w3,
                                              const float* __restrict__ wf,
                                              const float4* __restrict__ x) {
    int b = blockIdx.x, tid = threadIdx.x;
    if (b < 64) {                                   // abs-sum partials
        int t = b >> 4, j = b & 15;
        const float* p; int N;
        if      (t == 0) { p = w1; N = 1728;   }
        else if (t == 1) { p = w2; N = 73728;  }
        else if (t == 2) { p = w3; N = 294912; }
        else             { p = wf; N = 256000; }
        float s = 0.f;
        for (int i = j * 256 + tid; i < N; i += 16 * 256) s += fabsf(p[i]);
        __shared__ float sh[256];
        sh[tid] = s; __syncthreads();
        for (int k = 128; k > 0; k >>= 1) {
            if (tid < k) sh[tid] += sh[tid + k];
            __syncthreads();
        }
        if (tid == 0) g_partial[b] = sh[0];
    } else if (b == 64) {                           // pack w1
        if (tid < 64) {
            int o = tid;
            unsigned bb = 0;
            for (int t = 0; t < 27; t++) if (w1[o * 27 + t] < 0.f) bb |= 1u << t;
            g_w1b[o] = bb;
        }
    } else if (b < 74) {                            // pack w2: 2304 ids -> [jout][t][jin][oo]
        int id = (b - 65) * 256 + tid;
        if (id < 128 * 18) {
            int o = id / 18, r = id % 18, t = r >> 1, j = r & 1;
            unsigned bb = 0;
            for (int c = 0; c < 32; c++)
                if (w2[o * 576 + (j * 32 + c) * 9 + t] < 0.f) bb |= 1u << c;
            g_w2b[((o >> 5) * 18 + t * 2 + j) * 32 + (o & 31)] = bb;
        }
    } else if (b < 110) {                           // pack w3: 9216 ids -> [tapword][o]
        int id = (b - 74) * 256 + tid;
        if (id < 256 * 36) {
            int o = id / 36, r = id % 36, t = r >> 2, j = r & 3;
            unsigned bb = 0;
            for (int c = 0; c < 32; c++)
                if (w3[o * 1152 + (j * 32 + c) * 9 + t] < 0.f) bb |= 1u << c;
            g_w3b[r * 256 + o] = bb;                // i = t*4+j = r
        }
    } else if (b < 142) {                           // pack wf: 8000 ids
        int id = (b - 110) * 256 + tid;
        if (id < 1000 * 8) {
            int k = id / 8, j = id % 8;
            unsigned bb = 0;
            for (int c = 0; c < 32; c++)
                if (wf[k * 256 + j * 32 + c] < 0.f) bb |= 1u << c;
            g_wfb[k * 8 + j] = bb;
        }
    } else if (b < 730) {                           // pack x: 150528 words
        int w = (b - 142) * 256 + tid;
        const float4* p = x + (size_t)w * 8;
        unsigned bb = 0;
        #pragma unroll
        for (int i = 0; i < 8; i++) {
            float4 v = p[i];
            bb |= (unsigned)(v.x < 0.f) << (4 * i)
                | (unsigned)(v.y < 0.f) << (4 * i + 1)
                | (unsigned)(v.z < 0.f) << (4 * i + 2)
                | (unsigned)(v.w < 0.f) << (4 * i + 3);
        }
        g_xb[w] = bb;
    } else {                                        // zero conv3 accumulators: 8192 each
        int id = (b - 730) * 256 + tid;
        if (id < 8192) { g_s3[id] = 0; g_c3[id] = 0.f; }
    }
}

// ---------------- layer 1 from bits: 4 output px per thread, integer thresholds ----------------
__global__ void __launch_bounds__(128) k_conv1b(const float* __restrict__ b1) {
    __shared__ unsigned sw[64];                     // bits 0..26 weights, 27..31 threshold
    __shared__ float    sb[64];
    __shared__ float    sh_a;
    if (threadIdx.x == 0) sh_a = alpha2_of(0);
    if (threadIdx.x < 64) {
        int o = threadIdx.x;
        float a = alpha2_of(0);
        float bo = b1[o];
        int I0 = sign_thresh_I(a, bo);
        int thr = (28 - I0) >> 1;                   // ceil((27 - I0)/2), V=27 interior
        thr = thr < 0 ? 0 : (thr > 28 ? 28 : thr);
        sw[o] = (g_w1b[o] & 0x07FFFFFFu) | ((unsigned)thr << 27);
        sb[o] = bo;
    }
    __syncthreads();

    int t = blockIdx.x * 128 + threadIdx.x;         // 100352 exact
    int n = t / 3136, r = t % 3136;                 // 3136 = 112 rows * 28 groups
    int oh = r / 28, g = r % 28;
    int ow0 = g * 4;
    float a1sq = sh_a;

    int cb = 2 * ow0 - 1;                           // leftmost input col (may be -1)
    int a = cb >> 5;
    int shft = cb - (a << 5);

    unsigned long long W[9];
    #pragma unroll
    for (int ch = 0; ch < 3; ch++)
        #pragma unroll
        for (int kh = 0; kh < 3; kh++) {
            int ih = 2 * oh - 1 + kh;
            unsigned w0 = 0, w1 = 0;
            if (ih >= 0) {
                int rowbase = ((n * 3 + ch) * 224 + ih) * 7;
                if (a >= 0)     w0 = g_xb[rowbase + a];
                if (a + 1 <= 6) w1 = g_xb[rowbase + a + 1];
            }
            W[ch * 3 + kh] = ((unsigned long long)w1 << 32) | w0;
        }

    bool rowslow = (oh == 0);
    uint2* outp = g_a1b + (n * 112 + oh) * 112 + ow0;
    #pragma unroll
    for (int k = 0; k < 4; k++) {
        unsigned xb = 0;
        #pragma unroll
        for (int ch = 0; ch < 3; ch++)
            #pragma unroll
            for (int kh = 0; kh < 3; kh++) {
                unsigned bits = (unsigned)(W[ch * 3 + kh] >> (shft + 2 * k)) & 7u;
                xb |= bits << (ch * 9 + kh * 3);
            }
        unsigned wo0 = 0, wo1 = 0;
        if (!rowslow && !(k == 0 && ow0 == 0)) {    // interior: pure integer path
            #pragma unroll 4
            for (int o = 0; o < 32; o++) {
                unsigned wA = sw[o];
                int p = __popc((xb ^ wA) & 0x07FFFFFFu);
                wo0 |= (unsigned)(p >= (int)(wA >> 27)) << o;
                unsigned wB = sw[32 + o];
                int p1 = __popc((xb ^ wB) & 0x07FFFFFFu);
                wo1 |= (unsigned)(p1 >= (int)(wB >> 27)) << o;
            }
        } else {                                    // border: FP path (rare)
            unsigned mask = 0x7FFFFFFu;
            if (rowslow) mask &= ~0x1C0E07u;
            if (k == 0 && ow0 == 0) mask &= ~0x1249249u;
            int V = __popc(mask);
            #pragma unroll 4
            for (int o = 0; o < 32; o++) {
                int p = __popc((xb ^ sw[o]) & mask);
                float y = fmaf(a1sq, (float)(V - 2 * p), sb[o]);
                wo0 |= (unsigned)(y < 0.f) << o;
                int p1 = __popc((xb ^ sw[32 + o]) & mask);
                float y1 = fmaf(a1sq, (float)(V - 2 * p1), sb[32 + o]);
                wo1 |= (unsigned)(y1 < 0.f) << o;
            }
        }
        outp[k] = make_uint2(wo0, wo1);
    }
}

// ---------------- layer 2: ballot scheme, pixel pairs, integer thresholds ----------------
__global__ void __launch_bounds__(256, 5) k_conv2(const float* __restrict__ b2) {
    __shared__ uint2 srow[3][114];                  // input row tile, zero-padded
    __shared__ float sh_a;
    int blk = blockIdx.x;                           // 1792 = 32*56
    int n = blk / 56, oh = blk % 56;
    int tid = threadIdx.x, lane = tid & 31, w = tid >> 5;
    int jout = w & 3, half = w >> 2;

    if (tid == 0) sh_a = alpha2_of(1);
    for (int i = tid; i < 342; i += 256) {
        int kh = i / 114, col = i % 114;
        int ih = 2 * oh - 1 + kh, iw = col - 1;
        uint2 v = make_uint2(0u, 0u);
        if ((unsigned)ih < 112u && (unsigned)iw < 112u)
            v = g_a1b[(n * 112 + ih) * 112 + iw];
        srow[kh][col] = v;
    }

    unsigned wreg[18];
    #pragma unroll
    for (int i = 0; i < 18; i++) wreg[i] = g_w2b[(jout * 18 + i) * 32 + lane];
    float bb = b2[jout * 32 + lane];

    int pR = 0, pC = 0;
    #pragma unroll
    for (int t = 0; t < 3; t++) pR += __popc(wreg[t * 2]) + __popc(wreg[t * 2 + 1]);
    #pragma unroll
    for (int k = 0; k < 3; k++) pC += __popc(wreg[k * 6]) + __popc(wreg[k * 6 + 1]);
    int pT0 = __popc(wreg[0]) + __popc(wreg[1]);
    __syncthreads();

    float a2sq = sh_a;
    int rowflag = (oh == 0);
    int rAdj = rowflag ? pR : 0;
    int Vrow = rowflag ? 2 : 3;
    int I0 = sign_thresh_I(a2sq, bb);
    int thrA = (64 * Vrow * 3 + 2 * rAdj - I0 + 1) >> 1;      // interior cols
    int adj0 = rAdj + pC - (rowflag ? pT0 : 0);
    int thr0 = (64 * Vrow * 2 + 2 * adj0 - I0 + 1) >> 1;      // ow==0 column

    unsigned* outp = (unsigned*)g_a2b + (size_t)(n * 56 + oh) * 56 * 4 + jout;
    #pragma unroll 2
    for (int ip = 0; ip < 14; ip++) {
        int ow_a = half * 28 + 2 * ip;
        int b0 = 2 * ow_a;                          // smem col base; window cols b0..b0+4
        int P0 = 0, P1 = 0;
        #pragma unroll
        for (int kh = 0; kh < 3; kh++) {
            uint2 c0 = srow[kh][b0],     c1 = srow[kh][b0 + 1], c2 = srow[kh][b0 + 2];
            uint2 c3 = srow[kh][b0 + 3], c4 = srow[kh][b0 + 4];
            unsigned w0 = wreg[kh * 6],     w1 = wreg[kh * 6 + 1];
            unsigned w2 = wreg[kh * 6 + 2], w3 = wreg[kh * 6 + 3];
            unsigned w4 = wreg[kh * 6 + 4], w5 = wreg[kh * 6 + 5];
            P0 += __popc(c0.x ^ w0) + __popc(c0.y ^ w1)
                + __popc(c1.x ^ w2) + __popc(c1.y ^ w3)
                + __popc(c2.x ^ w4) + __popc(c2.y ^ w5);
            P1 += __popc(c2.x ^ w0) + __popc(c2.y ^ w1)
                + __popc(c3.x ^ w2) + __popc(c3.y ^ w3)
                + __popc(c4.x ^ w4) + __popc(c4.y ^ w5);
        }
        int thra = (half == 0 && ip == 0) ? thr0 : thrA;
        unsigned word0 = __ballot_sync(0xffffffffu, P0 >= thra);
        unsigned word1 = __ballot_sync(0xffffffffu, P1 >= thrA);
        if (lane == 0) {
            outp[ow_a * 4] = word0;
            outp[(ow_a + 1) * 4] = word1;
        }
    }
}

// ---------------- layer 3: lane=channel, weights in regs, row-tile in smem ----------------
// block = (n, oh): 896 blocks x 256 threads. thread = output channel.
__global__ void __launch_bounds__(256) k_conv3(const float* __restrict__ b3) {
    __shared__ uint4 st[3][57];                     // input row tile, zero-padded
    __shared__ float sh_a;
    int blk = blockIdx.x;                           // 896 = 32*28
    int n = blk / 28, oh = blk % 28;
    int tid = threadIdx.x;                          // = output channel
    if (tid == 0) sh_a = alpha2_of(2);

    for (int i = tid; i < 171; i += 256) {          // 3*57 entries
        int kh = i / 57, col = i % 57;
        int ih = 2 * oh - 1 + kh, iw = col - 1;
        uint4 v = make_uint4(0u, 0u, 0u, 0u);
        if ((unsigned)ih < 56u && (unsigned)iw < 56u)
            v = g_a2b[(n * 56 + ih) * 56 + iw];
        st[kh][col] = v;
    }

    unsigned wreg[36];                              // this channel's weights, coalesced
    #pragma unroll
    for (int i = 0; i < 36; i++) wreg[i] = g_w3b[i * 256 + tid];
    float bb = b3[tid];
    __syncthreads();

    float a3 = sh_a;
    int pR = 0, pC = 0, pT0 = 0;
    #pragma unroll
    for (int i = 0; i < 12; i++) pR += __popc(wreg[i]);             // taps 0,1,2
    #pragma unroll
    for (int k = 0; k < 3; k++)
        #pragma unroll
        for (int j = 0; j < 4; j++) pC += __popc(wreg[k * 12 + j]); // taps 0,3,6
    #pragma unroll
    for (int j = 0; j < 4; j++) pT0 += __popc(wreg[j]);

    int Ihi = max_I_leq(a3, bb, 1.f);               // y<=1  <=> I<=Ihi (exact)
    int Ilo = min_I_geq(a3, bb, -1.f);              // y>=-1 <=> I>=Ilo (exact)
    int rowflag = (oh == 0);
    int rAdj = rowflag ? pR : 0;
    int Vr = (rowflag ? 2 : 3) * 128;
    int Vint = Vr * 3, V0 = Vr * 2;
    int adj0 = rAdj + pC - (rowflag ? pT0 : 0);

    int acc = 0;
    float corr = 0.f;
    #pragma unroll 2
    for (int ow = 0; ow < 28; ow++) {
        int b0 = 2 * ow;
        int P = 0;
        #pragma unroll
        for (int kh = 0; kh < 3; kh++)
            #pragma unroll
            for (int kw = 0; kw < 3; kw++) {
                uint4 av = st[kh][b0 + kw];         // warp-uniform broadcast
                const int t4 = (kh * 3 + kw) * 4;
                P += __popc(av.x ^ wreg[t4]) + __popc(av.y ^ wreg[t4 + 1])
                   + __popc(av.z ^ wreg[t4 + 2]) + __popc(av.w ^ wreg[t4 + 3]);
            }
        int V   = (ow == 0) ? V0 : Vint;
        int adj = (ow == 0) ? adj0 : rAdj;
        int I = V - 2 * (P - adj);
        acc += I;
        if (I < Ilo || I > Ihi) {                   // exact clip screen; never in practice
            float y = fmaf(a3, (float)I, bb);
            corr += (y > 0.f ? 1.f : -1.f) - y;
        }
    }
    atomicAdd(&g_s3[n * 256 + tid], acc);           // integer: deterministic
    if (corr != 0.f) atomicAdd(&g_c3[n * 256 + tid], corr);
}

// ---------------- pooled sign: 32 blocks x 256 ch ----------------
__global__ void __launch_bounds__(256) k_pool(const float* __restrict__ b3) {
    __shared__ float sh_a;
    if (threadIdx.x == 0) sh_a = alpha2_of(2);
    __syncthreads();
    int n = blockIdx.x, c = threadIdx.x;
    float tail = 784.f * b3[c] + g_c3[n * 256 + c];
    float val = fmaf(sh_a, (float)g_s3[n * 256 + c], tail);
    unsigned m = __ballot_sync(0xffffffffu, val < 0.f);
    if ((c & 31) == 0) ((unsigned*)g_pb)[n * 8 + (c >> 5)] = m;
}

// ---------------- FC: out[n,k] = af^2 * (256 - 2P) + bf[k] ----------------
__global__ void __launch_bounds__(128) k_fc(const float* __restrict__ bf, float* __restrict__ out) {
    __shared__ float sh_a;
    if (threadIdx.x == 0) sh_a = alpha2_of(3);
    __syncthreads();
    int idx = blockIdx.x * 128 + threadIdx.x;
    if (idx >= 32000) return;
    int n = idx / 1000, k = idx % 1000;
    float afsq = sh_a;
    const uint4* pb = (const uint4*)(g_pb + n * 32);
    const uint4* wb = (const uint4*)(g_wfb + k * 8);
    uint4 p0 = pb[0], p1 = pb[1], w0 = wb[0], w1 = wb[1];
    int P = __popc(p0.x ^ w0.x) + __popc(p0.y ^ w0.y) + __popc(p0.z ^ w0.z) + __popc(p0.w ^ w0.w)
          + __popc(p1.x ^ w1.x) + __popc(p1.y ^ w1.y) + __popc(p1.z ^ w1.z) + __popc(p1.w ^ w1.w);
    out[idx] = fmaf(afsq, (float)(256 - 2 * P), bf[k]);
}

// ---------------- launch ----------------
extern "C" void kernel_launch(void* const* d_in, const int* in_sizes, int n_in,
                              void* d_out, int out_size) {
    const float* x  = (const float*)d_in[0];
    const float* w1 = (const float*)d_in[1];
    const float* b1 = (const float*)d_in[2];
    const float* w2 = (const float*)d_in[3];
    const float* b2 = (const float*)d_in[4];
    const float* w3 = (const float*)d_in[5];
    const float* b3 = (const float*)d_in[6];
    const float* wf = (const float*)d_in[7];
    const float* bf = (const float*)d_in[8];
    float* out = (float*)d_out;

    k_prep<<<762, 256>>>(w1, w2, w3, wf, (const float4*)x);
    k_conv1b<<<784, 128>>>(b1);
    k_conv2<<<1792, 256>>>(b2);
    k_conv3<<<896, 256>>>(b3);
    k_pool<<<32, 256>>>(b3);
    k_fc<<<250, 128>>>(bf, out);
}

// round 16
// speedup vs baseline: 2.4410x; 1.0019x over previous
#include <cuda_runtime.h>
#include <stdint.h>

// ---------------- scratch (static __device__, no allocs) ----------------
__device__ float    g_partial[64];
__device__ unsigned g_w1b[64];                     // 27 bits: c*9 + kh*3 + kw
__device__ unsigned g_w2b[128 * 18];               // [jout][tap][jin][oo]
__device__ unsigned g_w3b[256 * 36];               // [tapword i][o]  (i = t*4+jw)
__device__ __align__(16) unsigned g_wfb[1000 * 8]; // [k][j] 256 bits
__device__ unsigned g_xb[32 * 3 * 224 * 7];        // x sign bits: [n][ch][row][7 words]
__device__ uint2    g_a1b[32 * 112 * 112];         // layer1 sign bits, 64 ch
__device__ uint4    g_a2b[32 * 56 * 56];           // layer2 sign bits, 128 ch
__device__ int      g_s3[32 * 256];                // conv3 pooled integer sums
__device__ float    g_c3[32 * 256];                // conv3 clip corrections (0 in practice)
__device__ __align__(16) unsigned char g_pb[32 * 32]; // pooled sign bits, byte = 8 ch

// alpha^2 for layer t, recomputed deterministically from fixed-order partials
__device__ __forceinline__ float alpha2_of(int t) {
    float s = 0.f;
    #pragma unroll
    for (int j = 0; j < 16; j++) s += g_partial[t * 16 + j];
    const float Ns[4] = {1728.f, 73728.f, 294912.f, 256000.f};
    float a = s / Ns[t];
    return a * a;
}

// max integer I with fmaf(a, I, b) < 0   (a > 0, exact by fix-up)
__device__ __forceinline__ int sign_thresh_I(float a, float b) {
    float t = -b / a;
    t = fminf(fmaxf(t, -4000.f), 4000.f);
    int I0 = (int)floorf(t);
    #pragma unroll
    for (int it = 0; it < 2; it++) if (fmaf(a, (float)(I0 + 1), b) < 0.f) I0++;
    #pragma unroll
    for (int it = 0; it < 2; it++) if (fmaf(a, (float)I0, b) >= 0.f) I0--;
    return I0;
}
// max integer I with fmaf(a, I, b) <= lim
__device__ __forceinline__ int max_I_leq(float a, float b, float lim) {
    float t = (lim - b) / a;
    t = fminf(fmaxf(t, -4000.f), 4000.f);
    int I = (int)floorf(t);
    #pragma unroll
    for (int it = 0; it < 2; it++) if (fmaf(a, (float)(I + 1), b) <= lim) I++;
    #pragma unroll
    for (int it = 0; it < 2; it++) if (fmaf(a, (float)I, b) > lim) I--;
    return I;
}
// min integer I with fmaf(a, I, b) >= lim
__device__ __forceinline__ int min_I_geq(float a, float b, float lim) {
    float t = (lim - b) / a;
    t = fminf(fmaxf(t, -4000.f), 4000.f);
    int I = (int)ceilf(t);
    #pragma unroll
    for (int it = 0; it < 2; it++) if (fmaf(a, (float)(I - 1), b) >= lim) I--;
    #pragma unroll
    for (int it = 0; it < 2; it++) if (fmaf(a, (float)I, b) < lim) I++;
    return I;
}

// ---------------- prep: alpha partials + weight packing + x packing + zeroing ----------------
__global__ void __launch_bounds__(256) k_prep(const float* __restrict__ w1,
                                              const float* __restrict__ w2,
                                              const float* __restrict__ w3,
                                              const float* __restrict__ wf,
                                              const float4* __restrict__ x) {
    int b = blockIdx.x, tid = threadIdx.x;
    if (b < 64) {                                   // abs-sum partials
        int t = b >> 4, j = b & 15;
        const float* p; int N;
        if      (t == 0) { p = w1; N = 1728;   }
        else if (t == 1) { p = w2; N = 73728;  }
        else if (t == 2) { p = w3; N = 294912; }
        else             { p = wf; N = 256000; }
        float s = 0.f;
        for (int i = j * 256 + tid; i < N; i += 16 * 256) s += fabsf(p[i]);
        __shared__ float sh[256];
        sh[tid] = s; __syncthreads();
        for (int k = 128; k > 0; k >>= 1) {
            if (tid < k) sh[tid] += sh[tid + k];
            __syncthreads();
        }
        if (tid == 0) g_partial[b] = sh[0];
    } else if (b == 64) {                           // pack w1
        if (tid < 64) {
            int o = tid;
            unsigned bb = 0;
            for (int t = 0; t < 27; t++) if (w1[o * 27 + t] < 0.f) bb |= 1u << t;
            g_w1b[o] = bb;
        }
    } else if (b < 74) {                            // pack w2: 2304 ids -> [jout][t][jin][oo]
        int id = (b - 65) * 256 + tid;
        if (id < 128 * 18) {
            int o = id / 18, r = id % 18, t = r >> 1, j = r & 1;
            unsigned bb = 0;
            for (int c = 0; c < 32; c++)
                if (w2[o * 576 + (j * 32 + c) * 9 + t] < 0.f) bb |= 1u << c;
            g_w2b[((o >> 5) * 18 + t * 2 + j) * 32 + (o & 31)] = bb;
        }
    } else if (b < 110) {                           // pack w3: 9216 ids -> [tapword][o]
        int id = (b - 74) * 256 + tid;
        if (id < 256 * 36) {
            int o = id / 36, r = id % 36, t = r >> 2, j = r & 3;
            unsigned bb = 0;
            for (int c = 0; c < 32; c++)
                if (w3[o * 1152 + (j * 32 + c) * 9 + t] < 0.f) bb |= 1u << c;
            g_w3b[r * 256 + o] = bb;                // i = t*4+j = r
        }
    } else if (b < 142) {                           // pack wf: 8000 ids
        int id = (b - 110) * 256 + tid;
        if (id < 1000 * 8) {
            int k = id / 8, j = id % 8;
            unsigned bb = 0;
            for (int c = 0; c < 32; c++)
                if (wf[k * 256 + j * 32 + c] < 0.f) bb |= 1u << c;
            g_wfb[k * 8 + j] = bb;
        }
    } else if (b < 730) {                           // pack x: 150528 words
        int w = (b - 142) * 256 + tid;
        const float4* p = x + (size_t)w * 8;
        unsigned bb = 0;
        #pragma unroll
        for (int i = 0; i < 8; i++) {
            float4 v = p[i];
            bb |= (unsigned)(v.x < 0.f) << (4 * i)
                | (unsigned)(v.y < 0.f) << (4 * i + 1)
                | (unsigned)(v.z < 0.f) << (4 * i + 2)
                | (unsigned)(v.w < 0.f) << (4 * i + 3);
        }
        g_xb[w] = bb;
    } else {                                        // zero conv3 accumulators: 8192 each
        int id = (b - 730) * 256 + tid;
        if (id < 8192) { g_s3[id] = 0; g_c3[id] = 0.f; }
    }
}

// ---------------- layer 1 from bits: 4 output px per thread, integer thresholds ----------------
__global__ void __launch_bounds__(128) k_conv1b(const float* __restrict__ b1) {
    __shared__ unsigned sw[64];                     // bits 0..26 weights, 27..31 threshold
    __shared__ float    sb[64];
    __shared__ float    sh_a;
    if (threadIdx.x == 0) sh_a = alpha2_of(0);
    if (threadIdx.x < 64) {
        int o = threadIdx.x;
        float a = alpha2_of(0);
        float bo = b1[o];
        int I0 = sign_thresh_I(a, bo);
        int thr = (28 - I0) >> 1;                   // ceil((27 - I0)/2), V=27 interior
        thr = thr < 0 ? 0 : (thr > 28 ? 28 : thr);
        sw[o] = (g_w1b[o] & 0x07FFFFFFu) | ((unsigned)thr << 27);
        sb[o] = bo;
    }
    __syncthreads();

    int t = blockIdx.x * 128 + threadIdx.x;         // 100352 exact
    int n = t / 3136, r = t % 3136;                 // 3136 = 112 rows * 28 groups
    int oh = r / 28, g = r % 28;
    int ow0 = g * 4;
    float a1sq = sh_a;

    int cb = 2 * ow0 - 1;                           // leftmost input col (may be -1)
    int a = cb >> 5;
    int shft = cb - (a << 5);

    unsigned long long W[9];
    #pragma unroll
    for (int ch = 0; ch < 3; ch++)
        #pragma unroll
        for (int kh = 0; kh < 3; kh++) {
            int ih = 2 * oh - 1 + kh;
            unsigned w0 = 0, w1 = 0;
            if (ih >= 0) {
                int rowbase = ((n * 3 + ch) * 224 + ih) * 7;
                if (a >= 0)     w0 = g_xb[rowbase + a];
                if (a + 1 <= 6) w1 = g_xb[rowbase + a + 1];
            }
            W[ch * 3 + kh] = ((unsigned long long)w1 << 32) | w0;
        }

    bool rowslow = (oh == 0);
    uint2* outp = g_a1b + (n * 112 + oh) * 112 + ow0;
    #pragma unroll
    for (int k = 0; k < 4; k++) {
        unsigned xb = 0;
        #pragma unroll
        for (int ch = 0; ch < 3; ch++)
            #pragma unroll
            for (int kh = 0; kh < 3; kh++) {
                unsigned bits = (unsigned)(W[ch * 3 + kh] >> (shft + 2 * k)) & 7u;
                xb |= bits << (ch * 9 + kh * 3);
            }
        unsigned wo0 = 0, wo1 = 0;
        if (!rowslow && !(k == 0 && ow0 == 0)) {    // interior: pure integer path
            #pragma unroll 4
            for (int o = 0; o < 32; o++) {
                unsigned wA = sw[o];
                int p = __popc((xb ^ wA) & 0x07FFFFFFu);
                wo0 |= (unsigned)(p >= (int)(wA >> 27)) << o;
                unsigned wB = sw[32 + o];
                int p1 = __popc((xb ^ wB) & 0x07FFFFFFu);
                wo1 |= (unsigned)(p1 >= (int)(wB >> 27)) << o;
            }
        } else {                                    // border: FP path (rare)
            unsigned mask = 0x7FFFFFFu;
            if (rowslow) mask &= ~0x1C0E07u;
            if (k == 0 && ow0 == 0) mask &= ~0x1249249u;
            int V = __popc(mask);
            #pragma unroll 4
            for (int o = 0; o < 32; o++) {
                int p = __popc((xb ^ sw[o]) & mask);
                float y = fmaf(a1sq, (float)(V - 2 * p), sb[o]);
                wo0 |= (unsigned)(y < 0.f) << o;
                int p1 = __popc((xb ^ sw[32 + o]) & mask);
                float y1 = fmaf(a1sq, (float)(V - 2 * p1), sb[32 + o]);
                wo1 |= (unsigned)(y1 < 0.f) << o;
            }
        }
        outp[k] = make_uint2(wo0, wo1);
    }
}

// ---------------- layer 2: ballot scheme, 4 output rows per block (single wave) ----------------
// grid 448 = 32 n * 14 row-groups. 8 warps: jout = w&3, rh = w>>2 (2 rows each, ALL 56 cols).
__global__ void __launch_bounds__(256) k_conv2(const float* __restrict__ b2) {
    __shared__ uint2 st[9][114];                    // input rows 8rg-1 .. 8rg+7, cols -1..112
    __shared__ float sh_a;
    int blk = blockIdx.x;                           // 448
    int n = blk / 14, rg = blk % 14;
    int tid = threadIdx.x, lane = tid & 31, w = tid >> 5;
    int jout = w & 3, rh = w >> 2;

    if (tid == 0) sh_a = alpha2_of(1);
    for (int i = tid; i < 1026; i += 256) {         // 9*114
        int tr = i / 114, col = i % 114;
        int ih = 8 * rg - 1 + tr, iw = col - 1;
        uint2 v = make_uint2(0u, 0u);
        if ((unsigned)ih < 112u && (unsigned)iw < 112u)
            v = g_a1b[(n * 112 + ih) * 112 + iw];
        st[tr][col] = v;
    }

    unsigned wreg[18];
    #pragma unroll
    for (int i = 0; i < 18; i++) wreg[i] = g_w2b[(jout * 18 + i) * 32 + lane];
    float bb = b2[jout * 32 + lane];

    int pR = 0, pC = 0;
    #pragma unroll
    for (int t = 0; t < 3; t++) pR += __popc(wreg[t * 2]) + __popc(wreg[t * 2 + 1]);
    #pragma unroll
    for (int k = 0; k < 3; k++) pC += __popc(wreg[k * 6]) + __popc(wreg[k * 6 + 1]);
    int pT0 = __popc(wreg[0]) + __popc(wreg[1]);
    __syncthreads();

    float a2sq = sh_a;
    int I0 = sign_thresh_I(a2sq, bb);

    #pragma unroll
    for (int rr = 0; rr < 2; rr++) {
        int lr = 2 * rh + rr;                       // 0..3 within block
        int oh = 4 * rg + lr;
        int rowflag = (oh == 0);
        int rAdj = rowflag ? pR : 0;
        int Vrow = rowflag ? 2 : 3;
        int thrA = (64 * Vrow * 3 + 2 * rAdj - I0 + 1) >> 1;
        int adj0 = rAdj + pC - (rowflag ? pT0 : 0);
        int thr0 = (64 * Vrow * 2 + 2 * adj0 - I0 + 1) >> 1;
        int trb = 2 * lr;                           // tile row base for kh=0

        unsigned* outp = (unsigned*)g_a2b + (size_t)(n * 56 + oh) * 56 * 4 + jout;
        #pragma unroll 2
        for (int ip = 0; ip < 28; ip++) {           // ALL 56 columns (2 per iter)
            int ow_a = 2 * ip;
            int b0 = 2 * ow_a;                      // smem col base; window cols b0..b0+4
            int P0 = 0, P1 = 0;
            #pragma unroll
            for (int kh = 0; kh < 3; kh++) {
                const uint2* row = st[trb + kh];
                uint2 c0 = row[b0],     c1 = row[b0 + 1], c2 = row[b0 + 2];
                uint2 c3 = row[b0 + 3], c4 = row[b0 + 4];
                unsigned w0 = wreg[kh * 6],     w1 = wreg[kh * 6 + 1];
                unsigned w2 = wreg[kh * 6 + 2], w3 = wreg[kh * 6 + 3];
                unsigned w4 = wreg[kh * 6 + 4], w5 = wreg[kh * 6 + 5];
                P0 += __popc(c0.x ^ w0) + __popc(c0.y ^ w1)
                    + __popc(c1.x ^ w2) + __popc(c1.y ^ w3)
                    + __popc(c2.x ^ w4) + __popc(c2.y ^ w5);
                P1 += __popc(c2.x ^ w0) + __popc(c2.y ^ w1)
                    + __popc(c3.x ^ w2) + __popc(c3.y ^ w3)
                    + __popc(c4.x ^ w4) + __popc(c4.y ^ w5);
            }
            int thra = (ip == 0) ? thr0 : thrA;
            unsigned word0 = __ballot_sync(0xffffffffu, P0 >= thra);
            unsigned word1 = __ballot_sync(0xffffffffu, P1 >= thrA);
            if (lane == 0) {
                outp[ow_a * 4] = word0;
                outp[(ow_a + 1) * 4] = word1;
            }
        }
    }
}

// ---------------- layer 3: lane=channel, 2 output rows per block (single wave) ----------------
// grid 448 = 32 n * 14 row-groups. thread = output channel.
__global__ void __launch_bounds__(256) k_conv3(const float* __restrict__ b3) {
    __shared__ uint4 st[5][57];                     // input rows 4rg-1 .. 4rg+3, cols -1..55
    __shared__ float sh_a;
    int blk = blockIdx.x;                           // 448
    int n = blk / 14, rg = blk % 14;
    int tid = threadIdx.x;                          // = output channel
    if (tid == 0) sh_a = alpha2_of(2);

    for (int i = tid; i < 285; i += 256) {          // 5*57
        int tr = i / 57, col = i % 57;
        int ih = 4 * rg - 1 + tr, iw = col - 1;
        uint4 v = make_uint4(0u, 0u, 0u, 0u);
        if ((unsigned)ih < 56u && (unsigned)iw < 56u)
            v = g_a2b[(n * 56 + ih) * 56 + iw];
        st[tr][col] = v;
    }

    unsigned wreg[36];                              // this channel's weights, coalesced
    #pragma unroll
    for (int i = 0; i < 36; i++) wreg[i] = g_w3b[i * 256 + tid];
    float bb = b3[tid];
    __syncthreads();

    float a3 = sh_a;
    int pR = 0, pC = 0, pT0 = 0;
    #pragma unroll
    for (int i = 0; i < 12; i++) pR += __popc(wreg[i]);             // taps 0,1,2
    #pragma unroll
    for (int k = 0; k < 3; k++)
        #pragma unroll
        for (int j = 0; j < 4; j++) pC += __popc(wreg[k * 12 + j]); // taps 0,3,6
    #pragma unroll
    for (int j = 0; j < 4; j++) pT0 += __popc(wreg[j]);

    int Ihi = max_I_leq(a3, bb, 1.f);               // y<=1  <=> I<=Ihi (exact)
    int Ilo = min_I_geq(a3, bb, -1.f);              // y>=-1 <=> I>=Ilo (exact)

    int acc = 0;
    float corr = 0.f;
    #pragma unroll
    for (int lr = 0; lr < 2; lr++) {
        int oh = 2 * rg + lr;
        int rowflag = (oh == 0);
        int rAdj = rowflag ? pR : 0;
        int Vr = (rowflag ? 2 : 3) * 128;
        int Vint = Vr * 3, V0 = Vr * 2;
        int adj0 = rAdj + pC - (rowflag ? pT0 : 0);
        int trb = 2 * lr;                           // tile row base for kh=0

        #pragma unroll 2
        for (int ow = 0; ow < 28; ow++) {
            int b0 = 2 * ow;
            int P = 0;
            #pragma unroll
            for (int kh = 0; kh < 3; kh++)
                #pragma unroll
                for (int kw = 0; kw < 3; kw++) {
                    uint4 av = st[trb + kh][b0 + kw];   // warp-uniform broadcast
                    const int t4 = (kh * 3 + kw) * 4;
                    P += __popc(av.x ^ wreg[t4]) + __popc(av.y ^ wreg[t4 + 1])
                       + __popc(av.z ^ wreg[t4 + 2]) + __popc(av.w ^ wreg[t4 + 3]);
                }
            int V   = (ow == 0) ? V0 : Vint;
            int adj = (ow == 0) ? adj0 : rAdj;
            int I = V - 2 * (P - adj);
            acc += I;
            if (I < Ilo || I > Ihi) {               // exact clip screen; never in practice
                float y = fmaf(a3, (float)I, bb);
                corr += (y > 0.f ? 1.f : -1.f) - y;
            }
        }
    }
    atomicAdd(&g_s3[n * 256 + tid], acc);           // integer: deterministic
    if (corr != 0.f) atomicAdd(&g_c3[n * 256 + tid], corr);
}

// ---------------- pooled sign: 32 blocks x 256 ch ----------------
__global__ void __launch_bounds__(256) k_pool(const float* __restrict__ b3) {
    __shared__ float sh_a;
    if (threadIdx.x == 0) sh_a = alpha2_of(2);
    __syncthreads();
    int n = blockIdx.x, c = threadIdx.x;
    float tail = 784.f * b3[c] + g_c3[n * 256 + c];
    float val = fmaf(sh_a, (float)g_s3[n * 256 + c], tail);
    unsigned m = __ballot_sync(0xffffffffu, val < 0.f);
    if ((c & 31) == 0) ((unsigned*)g_pb)[n * 8 + (c >> 5)] = m;
}

// ---------------- FC: out[n,k] = af^2 * (256 - 2P) + bf[k] ----------------
__global__ void __launch_bounds__(128) k_fc(const float* __restrict__ bf, float* __restrict__ out) {
    __shared__ float sh_a;
    if (threadIdx.x == 0) sh_a = alpha2_of(3);
    __syncthreads();
    int idx = blockIdx.x * 128 + threadIdx.x;
    if (idx >= 32000) return;
    int n = idx / 1000, k = idx % 1000;
    float afsq = sh_a;
    const uint4* pb = (const uint4*)(g_pb + n * 32);
    const uint4* wb = (const uint4*)(g_wfb + k * 8);
    uint4 p0 = pb[0], p1 = pb[1], w0 = wb[0], w1 = wb[1];
    int P = __popc(p0.x ^ w0.x) + __popc(p0.y ^ w0.y) + __popc(p0.z ^ w0.z) + __popc(p0.w ^ w0.w)
          + __popc(p1.x ^ w1.x) + __popc(p1.y ^ w1.y) + __popc(p1.z ^ w1.z) + __popc(p1.w ^ w1.w);
    out[idx] = fmaf(afsq, (float)(256 - 2 * P), bf[k]);
}

// ---------------- launch ----------------
extern "C" void kernel_launch(void* const* d_in, const int* in_sizes, int n_in,
                              void* d_out, int out_size) {
    const float* x  = (const float*)d_in[0];
    const float* w1 = (const float*)d_in[1];
    const float* b1 = (const float*)d_in[2];
    const float* w2 = (const float*)d_in[3];
    const float* b2 = (const float*)d_in[4];
    const float* w3 = (const float*)d_in[5];
    const float* b3 = (const float*)d_in[6];
    const float* wf = (const float*)d_in[7];
    const float* bf = (const float*)d_in[8];
    float* out = (float*)d_out;

    k_prep<<<762, 256>>>(w1, w2, w3, wf, (const float4*)x);
    k_conv1b<<<784, 128>>>(b1);
    k_conv2<<<448, 256>>>(b2);
    k_conv3<<<448, 256>>>(b3);
    k_pool<<<32, 256>>>(b3);
    k_fc<<<250, 128>>>(bf, out);
}